// round 8
// baseline (speedup 1.0000x reference)
#include <cuda_runtime.h>
#include <math.h>

#define D_MODEL 1024
#define NHEADS  16
#define HDIM    64
#define SEQ     4096
#define BATCH   4
#define MROWS   (BATCH * SEQ)   // 16384

// ---------------------------------------------------------------------------
// Scratch (device globals: allocation-free per harness rules)
// ---------------------------------------------------------------------------
__device__ float g_Q[(size_t)MROWS * D_MODEL];
__device__ float g_K[(size_t)MROWS * D_MODEL];
__device__ float g_V[(size_t)MROWS * D_MODEL];
__device__ float g_ATT[(size_t)MROWS * D_MODEL];
__device__ float g_VK[BATCH * NHEADS * 65 * 64];
__device__ float g_cos[SEQ * 32];
__device__ float g_sin[SEQ * 32];

// ---------------------------------------------------------------------------
// RoPE table: cos/sin computed once in fp64 for accuracy
// ---------------------------------------------------------------------------
__global__ void rope_table_kernel() {
    int idx = blockIdx.x * blockDim.x + threadIdx.x;
    if (idx >= SEQ * 32) return;
    int s = idx >> 5;
    int p = idx & 31;
    // freq = 10000^(-(2p)/64)
    double freq = exp(-((double)(2 * p) / 64.0) * 9.210340371976184); // ln(10000)
    double ang = (double)s * freq;
    g_cos[idx] = (float)cos(ang);
    g_sin[idx] = (float)sin(ang);
}

// ---------------------------------------------------------------------------
// Tiled SGEMM: C[M,N] = A[M,K] @ B[K,N], fp32.
// BM=128, BN=128, BK=16, 256 threads, 8x8 microtile per thread.
// ep=1: fuse RoPE (interleaved pairs, per 64-wide head) + ReLU into epilogue.
// ---------------------------------------------------------------------------
#define BM 128
#define BN 128
#define BK 16
#define TM 8
#define TN 8

__global__ __launch_bounds__(256)
void sgemm_ep(const float* __restrict__ A, const float* __restrict__ B,
              float* __restrict__ C, int M, int N, int K, int ep)
{
    __shared__ float As[BK][BM];   // A tile, transposed
    __shared__ float Bs[BK][BN];

    const int brow = blockIdx.y;
    const int bcol = blockIdx.x;
    const int tid  = threadIdx.x;
    const int trow = tid >> 4;     // 0..15
    const int tcol = tid & 15;     // 0..15

    const float* Ab = A + (size_t)brow * BM * K;
    const float* Bb = B + (size_t)bcol * BN;

    // A loads: 128 rows x 16 cols = 512 float4; 2 per thread
    const int a_r = tid >> 2;          // 0..63 (rows a_r, a_r+64)
    const int a_c = (tid & 3) * 4;     // 0,4,8,12
    // B loads: 16 rows x 128 cols = 512 float4; 2 per thread
    const int b_r = tid >> 5;          // 0..7 (rows b_r, b_r+8)
    const int b_c = (tid & 31) * 4;    // 0..124

    float acc[TM][TN];
#pragma unroll
    for (int i = 0; i < TM; i++)
#pragma unroll
        for (int j = 0; j < TN; j++) acc[i][j] = 0.0f;

    float a_frag[TM], b_frag[TN];

    for (int k0 = 0; k0 < K; k0 += BK) {
#pragma unroll
        for (int i = 0; i < 2; i++) {
            float4 t = *(const float4*)(Ab + (size_t)(a_r + i * 64) * K + k0 + a_c);
            As[a_c + 0][a_r + i * 64] = t.x;
            As[a_c + 1][a_r + i * 64] = t.y;
            As[a_c + 2][a_r + i * 64] = t.z;
            As[a_c + 3][a_r + i * 64] = t.w;
        }
#pragma unroll
        for (int i = 0; i < 2; i++) {
            *(float4*)(&Bs[b_r + i * 8][b_c]) =
                *(const float4*)(Bb + (size_t)(k0 + b_r + i * 8) * N + b_c);
        }
        __syncthreads();

#pragma unroll
        for (int kk = 0; kk < BK; kk++) {
#pragma unroll
            for (int i = 0; i < TM; i++) a_frag[i] = As[kk][trow * TM + i];
#pragma unroll
            for (int j = 0; j < TN; j++) b_frag[j] = Bs[kk][tcol * TN + j];
#pragma unroll
            for (int i = 0; i < TM; i++)
#pragma unroll
                for (int j = 0; j < TN; j++)
                    acc[i][j] = fmaf(a_frag[i], b_frag[j], acc[i][j]);
        }
        __syncthreads();
    }

    const int crow0 = brow * BM + trow * TM;
    const int ccol0 = bcol * BN + tcol * TN;

    if (ep == 1) {
        // RoPE (interleaved pairs within each 64-wide head) + ReLU
#pragma unroll
        for (int i = 0; i < TM; i++) {
            int row = crow0 + i;
            int s = row & (SEQ - 1);
#pragma unroll
            for (int j = 0; j < TN; j += 2) {
                int c = ccol0 + j;
                int p = (c & 63) >> 1;       // pair index within head
                float cs = g_cos[s * 32 + p];
                float sn = g_sin[s * 32 + p];
                float x1 = acc[i][j];
                float x2 = acc[i][j + 1];
                float r1 = x1 * cs - x2 * sn;
                float r2 = fmaf(x1, sn, x2 * cs);
                acc[i][j]     = fmaxf(r1, 0.0f);
                acc[i][j + 1] = fmaxf(r2, 0.0f);
            }
        }
    }

#pragma unroll
    for (int i = 0; i < TM; i++) {
        float4* cp = (float4*)(C + (size_t)(crow0 + i) * N + ccol0);
        cp[0] = make_float4(acc[i][0], acc[i][1], acc[i][2], acc[i][3]);
        cp[1] = make_float4(acc[i][4], acc[i][5], acc[i][6], acc[i][7]);
    }
}

// ---------------------------------------------------------------------------
// vk[b,h,e,d] = sum_s vpad[b,h,s,e] * k[b,h,s,d]   (e<64: v; e==64: vpad==1)
// One CTA per (b,h). Outer-product accumulation over 64-row chunks.
// ---------------------------------------------------------------------------
__global__ __launch_bounds__(256)
void vk_kernel()
{
    __shared__ float ks[64][64];
    __shared__ float vs[64][64];

    const int bh = blockIdx.x;
    const int b = bh >> 4;
    const int h = bh & 15;
    const int t = threadIdx.x;
    const int d  = t & 63;     // column of k
    const int eg = t >> 6;     // 0..3: e group (e = eg*16 + j)

    const size_t base = (size_t)b * SEQ * D_MODEL + (size_t)h * 64;

    float acc[16];
#pragma unroll
    for (int j = 0; j < 16; j++) acc[j] = 0.0f;
    float ksum = 0.0f;

    for (int c = 0; c < SEQ / 64; c++) {
        for (int i = t; i < 64 * 64; i += 256) {
            int row = i >> 6, col = i & 63;
            size_t goff = base + (size_t)(c * 64 + row) * D_MODEL + col;
            ks[row][col] = g_K[goff];
            vs[row][col] = g_V[goff];
        }
        __syncthreads();
#pragma unroll 4
        for (int ss = 0; ss < 64; ss++) {
            float kv = ks[ss][d];
            if (eg == 0) ksum += kv;
#pragma unroll
            for (int j = 0; j < 16; j++)
                acc[j] = fmaf(vs[ss][eg * 16 + j], kv, acc[j]);
        }
        __syncthreads();
    }

    float* vkp = g_VK + (size_t)bh * 65 * 64;
#pragma unroll
    for (int j = 0; j < 16; j++)
        vkp[(eg * 16 + j) * 64 + d] = acc[j];
    if (eg == 0)
        vkp[64 * 64 + d] = ksum;
}

// ---------------------------------------------------------------------------
// attn[b,h,l,e] = (sum_d vk[e,d]*q[l,d]) / (sum_d vk[64,d]*q[l,d] + eps)
// grid = (64 bh, 16 l-chunks), 256 threads; one token row per thread.
// Output written as (b*S+l, h*64+e) row-major -> feeds final GEMM directly.
// ---------------------------------------------------------------------------
__global__ __launch_bounds__(256)
void attn_kernel()
{
    __shared__ float vkS[65][64];
    const int bh = blockIdx.x;
    const int b = bh >> 4;
    const int h = bh & 15;
    const int t = threadIdx.x;

    const float* vkp = g_VK + (size_t)bh * 65 * 64;
    for (int i = t; i < 65 * 64; i += 256)
        vkS[i >> 6][i & 63] = vkp[i];
    __syncthreads();

    const int l = blockIdx.y * 256 + t;
    const size_t roff = ((size_t)(b * SEQ + l)) * D_MODEL + (size_t)h * 64;
    const float* qr = g_Q + roff;

    float q[64];
#pragma unroll
    for (int i = 0; i < 16; i++) {
        float4 v4 = ((const float4*)qr)[i];
        q[4 * i + 0] = v4.x; q[4 * i + 1] = v4.y;
        q[4 * i + 2] = v4.z; q[4 * i + 3] = v4.w;
    }

    float denom = 1e-6f;
#pragma unroll
    for (int d = 0; d < 64; d++) denom = fmaf(vkS[64][d], q[d], denom);
    float inv = 1.0f / denom;

    float* orow = g_ATT + roff;
    for (int e = 0; e < 64; e++) {
        float num = 0.0f;
#pragma unroll
        for (int d = 0; d < 64; d++) num = fmaf(vkS[e][d], q[d], num);
        orow[e] = num * inv;
    }
}

// ---------------------------------------------------------------------------
// kernel_launch
// ---------------------------------------------------------------------------
extern "C" void kernel_launch(void* const* d_in, const int* in_sizes, int n_in,
                              void* d_out, int out_size)
{
    const float* x  = (const float*)d_in[0];
    const float* Wq = (const float*)d_in[1];
    const float* Wk = (const float*)d_in[2];
    const float* Wv = (const float*)d_in[3];
    const float* Wo = (const float*)d_in[4];
    float* out = (float*)d_out;

    float *qp, *kp, *vp, *ap;
    cudaGetSymbolAddress((void**)&qp, g_Q);
    cudaGetSymbolAddress((void**)&kp, g_K);
    cudaGetSymbolAddress((void**)&vp, g_V);
    cudaGetSymbolAddress((void**)&ap, g_ATT);

    rope_table_kernel<<<(SEQ * 32 + 255) / 256, 256>>>();

    dim3 grid(D_MODEL / BN, MROWS / BM);
    sgemm_ep<<<grid, 256>>>(x, Wq, qp, MROWS, D_MODEL, D_MODEL, 1);
    sgemm_ep<<<grid, 256>>>(x, Wk, kp, MROWS, D_MODEL, D_MODEL, 1);
    sgemm_ep<<<grid, 256>>>(x, Wv, vp, MROWS, D_MODEL, D_MODEL, 0);

    vk_kernel<<<BATCH * NHEADS, 256>>>();
    attn_kernel<<<dim3(BATCH * NHEADS, SEQ / 256), 256>>>();

    sgemm_ep<<<grid, 256>>>(ap, Wo, out, MROWS, D_MODEL, D_MODEL, 0);
}

// round 9
// speedup vs baseline: 1.0036x; 1.0036x over previous
#include <cuda_runtime.h>
#include <math.h>

#define D_MODEL 1024
#define NHEADS  16
#define HDIM    64
#define SEQ     4096
#define BATCH   4
#define MROWS   (BATCH * SEQ)   // 16384

// ---------------------------------------------------------------------------
// Scratch (device globals: allocation-free per harness rules)
// ---------------------------------------------------------------------------
__device__ float g_Q[(size_t)MROWS * D_MODEL];
__device__ float g_K[(size_t)MROWS * D_MODEL];
__device__ float g_V[(size_t)MROWS * D_MODEL];
__device__ float g_ATT[(size_t)MROWS * D_MODEL];
__device__ float g_VK[BATCH * NHEADS * 65 * 64];
__device__ float g_cos[SEQ * 32];
__device__ float g_sin[SEQ * 32];

// ---------------------------------------------------------------------------
// RoPE table: cos/sin computed once in fp64 for accuracy
// ---------------------------------------------------------------------------
__global__ void rope_table_kernel() {
    int idx = blockIdx.x * blockDim.x + threadIdx.x;
    if (idx >= SEQ * 32) return;
    int s = idx >> 5;
    int p = idx & 31;
    // freq = 10000^(-(2p)/64)
    double freq = exp(-((double)(2 * p) / 64.0) * 9.210340371976184); // ln(10000)
    double ang = (double)s * freq;
    g_cos[idx] = (float)cos(ang);
    g_sin[idx] = (float)sin(ang);
}

// ---------------------------------------------------------------------------
// Tiled SGEMM: C[M,N] = A[M,K] @ B[K,N], fp32.
// BM=128, BN=128, BK=16, 256 threads, 8x8 microtile per thread.
// ep=1: fuse RoPE (interleaved pairs, per 64-wide head) + ReLU into epilogue.
// ---------------------------------------------------------------------------
#define BM 128
#define BN 128
#define BK 16
#define TM 8
#define TN 8

__global__ __launch_bounds__(256)
void sgemm_ep(const float* __restrict__ A, const float* __restrict__ B,
              float* __restrict__ C, int M, int N, int K, int ep)
{
    __shared__ float As[BK][BM];   // A tile, transposed
    __shared__ float Bs[BK][BN];

    const int brow = blockIdx.y;
    const int bcol = blockIdx.x;
    const int tid  = threadIdx.x;
    const int trow = tid >> 4;     // 0..15
    const int tcol = tid & 15;     // 0..15

    const float* Ab = A + (size_t)brow * BM * K;
    const float* Bb = B + (size_t)bcol * BN;

    // A loads: 128 rows x 16 cols = 512 float4; 2 per thread
    const int a_r = tid >> 2;          // 0..63 (rows a_r, a_r+64)
    const int a_c = (tid & 3) * 4;     // 0,4,8,12
    // B loads: 16 rows x 128 cols = 512 float4; 2 per thread
    const int b_r = tid >> 5;          // 0..7 (rows b_r, b_r+8)
    const int b_c = (tid & 31) * 4;    // 0..124

    float acc[TM][TN];
#pragma unroll
    for (int i = 0; i < TM; i++)
#pragma unroll
        for (int j = 0; j < TN; j++) acc[i][j] = 0.0f;

    float a_frag[TM], b_frag[TN];

    for (int k0 = 0; k0 < K; k0 += BK) {
#pragma unroll
        for (int i = 0; i < 2; i++) {
            float4 t = *(const float4*)(Ab + (size_t)(a_r + i * 64) * K + k0 + a_c);
            As[a_c + 0][a_r + i * 64] = t.x;
            As[a_c + 1][a_r + i * 64] = t.y;
            As[a_c + 2][a_r + i * 64] = t.z;
            As[a_c + 3][a_r + i * 64] = t.w;
        }
#pragma unroll
        for (int i = 0; i < 2; i++) {
            *(float4*)(&Bs[b_r + i * 8][b_c]) =
                *(const float4*)(Bb + (size_t)(k0 + b_r + i * 8) * N + b_c);
        }
        __syncthreads();

#pragma unroll
        for (int kk = 0; kk < BK; kk++) {
#pragma unroll
            for (int i = 0; i < TM; i++) a_frag[i] = As[kk][trow * TM + i];
#pragma unroll
            for (int j = 0; j < TN; j++) b_frag[j] = Bs[kk][tcol * TN + j];
#pragma unroll
            for (int i = 0; i < TM; i++)
#pragma unroll
                for (int j = 0; j < TN; j++)
                    acc[i][j] = fmaf(a_frag[i], b_frag[j], acc[i][j]);
        }
        __syncthreads();
    }

    const int crow0 = brow * BM + trow * TM;
    const int ccol0 = bcol * BN + tcol * TN;

    if (ep == 1) {
        // RoPE (interleaved pairs within each 64-wide head) + ReLU
#pragma unroll
        for (int i = 0; i < TM; i++) {
            int row = crow0 + i;
            int s = row & (SEQ - 1);
#pragma unroll
            for (int j = 0; j < TN; j += 2) {
                int c = ccol0 + j;
                int p = (c & 63) >> 1;       // pair index within head
                float cs = g_cos[s * 32 + p];
                float sn = g_sin[s * 32 + p];
                float x1 = acc[i][j];
                float x2 = acc[i][j + 1];
                float r1 = x1 * cs - x2 * sn;
                float r2 = fmaf(x1, sn, x2 * cs);
                acc[i][j]     = fmaxf(r1, 0.0f);
                acc[i][j + 1] = fmaxf(r2, 0.0f);
            }
        }
    }

#pragma unroll
    for (int i = 0; i < TM; i++) {
        float4* cp = (float4*)(C + (size_t)(crow0 + i) * N + ccol0);
        cp[0] = make_float4(acc[i][0], acc[i][1], acc[i][2], acc[i][3]);
        cp[1] = make_float4(acc[i][4], acc[i][5], acc[i][6], acc[i][7]);
    }
}

// ---------------------------------------------------------------------------
// vk[b,h,e,d] = sum_s vpad[b,h,s,e] * k[b,h,s,d]   (e<64: v; e==64: vpad==1)
// One CTA per (b,h). Outer-product accumulation over 64-row chunks.
// ---------------------------------------------------------------------------
__global__ __launch_bounds__(256)
void vk_kernel()
{
    __shared__ float ks[64][64];
    __shared__ float vs[64][64];

    const int bh = blockIdx.x;
    const int b = bh >> 4;
    const int h = bh & 15;
    const int t = threadIdx.x;
    const int d  = t & 63;     // column of k
    const int eg = t >> 6;     // 0..3: e group (e = eg*16 + j)

    const size_t base = (size_t)b * SEQ * D_MODEL + (size_t)h * 64;

    float acc[16];
#pragma unroll
    for (int j = 0; j < 16; j++) acc[j] = 0.0f;
    float ksum = 0.0f;

    for (int c = 0; c < SEQ / 64; c++) {
        for (int i = t; i < 64 * 64; i += 256) {
            int row = i >> 6, col = i & 63;
            size_t goff = base + (size_t)(c * 64 + row) * D_MODEL + col;
            ks[row][col] = g_K[goff];
            vs[row][col] = g_V[goff];
        }
        __syncthreads();
#pragma unroll 4
        for (int ss = 0; ss < 64; ss++) {
            float kv = ks[ss][d];
            if (eg == 0) ksum += kv;
#pragma unroll
            for (int j = 0; j < 16; j++)
                acc[j] = fmaf(vs[ss][eg * 16 + j], kv, acc[j]);
        }
        __syncthreads();
    }

    float* vkp = g_VK + (size_t)bh * 65 * 64;
#pragma unroll
    for (int j = 0; j < 16; j++)
        vkp[(eg * 16 + j) * 64 + d] = acc[j];
    if (eg == 0)
        vkp[64 * 64 + d] = ksum;
}

// ---------------------------------------------------------------------------
// attn[b,h,l,e] = (sum_d vk[e,d]*q[l,d]) / (sum_d vk[64,d]*q[l,d] + eps)
// grid = (64 bh, 16 l-chunks), 256 threads; one token row per thread.
// Output written as (b*S+l, h*64+e) row-major -> feeds final GEMM directly.
// ---------------------------------------------------------------------------
__global__ __launch_bounds__(256)
void attn_kernel()
{
    __shared__ float vkS[65][64];
    const int bh = blockIdx.x;
    const int b = bh >> 4;
    const int h = bh & 15;
    const int t = threadIdx.x;

    const float* vkp = g_VK + (size_t)bh * 65 * 64;
    for (int i = t; i < 65 * 64; i += 256)
        vkS[i >> 6][i & 63] = vkp[i];
    __syncthreads();

    const int l = blockIdx.y * 256 + t;
    const size_t roff = ((size_t)(b * SEQ + l)) * D_MODEL + (size_t)h * 64;
    const float* qr = g_Q + roff;

    float q[64];
#pragma unroll
    for (int i = 0; i < 16; i++) {
        float4 v4 = ((const float4*)qr)[i];
        q[4 * i + 0] = v4.x; q[4 * i + 1] = v4.y;
        q[4 * i + 2] = v4.z; q[4 * i + 3] = v4.w;
    }

    float denom = 1e-6f;
#pragma unroll
    for (int d = 0; d < 64; d++) denom = fmaf(vkS[64][d], q[d], denom);
    float inv = 1.0f / denom;

    float* orow = g_ATT + roff;
    for (int e = 0; e < 64; e++) {
        float num = 0.0f;
#pragma unroll
        for (int d = 0; d < 64; d++) num = fmaf(vkS[e][d], q[d], num);
        orow[e] = num * inv;
    }
}

// ---------------------------------------------------------------------------
// kernel_launch
// ---------------------------------------------------------------------------
extern "C" void kernel_launch(void* const* d_in, const int* in_sizes, int n_in,
                              void* d_out, int out_size)
{
    const float* x  = (const float*)d_in[0];
    const float* Wq = (const float*)d_in[1];
    const float* Wk = (const float*)d_in[2];
    const float* Wv = (const float*)d_in[3];
    const float* Wo = (const float*)d_in[4];
    float* out = (float*)d_out;

    float *qp, *kp, *vp, *ap;
    cudaGetSymbolAddress((void**)&qp, g_Q);
    cudaGetSymbolAddress((void**)&kp, g_K);
    cudaGetSymbolAddress((void**)&vp, g_V);
    cudaGetSymbolAddress((void**)&ap, g_ATT);

    rope_table_kernel<<<(SEQ * 32 + 255) / 256, 256>>>();

    dim3 grid(D_MODEL / BN, MROWS / BM);
    sgemm_ep<<<grid, 256>>>(x, Wq, qp, MROWS, D_MODEL, D_MODEL, 1);
    sgemm_ep<<<grid, 256>>>(x, Wk, kp, MROWS, D_MODEL, D_MODEL, 1);
    sgemm_ep<<<grid, 256>>>(x, Wv, vp, MROWS, D_MODEL, D_MODEL, 0);

    vk_kernel<<<BATCH * NHEADS, 256>>>();
    attn_kernel<<<dim3(BATCH * NHEADS, SEQ / 256), 256>>>();

    sgemm_ep<<<grid, 256>>>(ap, Wo, out, MROWS, D_MODEL, D_MODEL, 0);
}

// round 15
// speedup vs baseline: 2.2451x; 2.2371x over previous
#include <cuda_runtime.h>
#include <cuda_bf16.h>
#include <math.h>
#include <stdint.h>

#define D_MODEL 1024
#define NHEADS  16
#define SEQ     4096
#define BATCH   4
#define MROWS   (BATCH * SEQ)   // 16384

// ---------------------------------------------------------------------------
// Scratch (device globals: allocation-free per harness rules)
// ---------------------------------------------------------------------------
__device__ float g_Q[(size_t)MROWS * D_MODEL];
__device__ float g_K[(size_t)MROWS * D_MODEL];
__device__ float g_V[(size_t)MROWS * D_MODEL];
__device__ __nv_bfloat16 g_Xh[(size_t)MROWS * D_MODEL];
__device__ __nv_bfloat16 g_Xl[(size_t)MROWS * D_MODEL];
__device__ __nv_bfloat16 g_Ah[(size_t)MROWS * D_MODEL];
__device__ __nv_bfloat16 g_Al[(size_t)MROWS * D_MODEL];
__device__ __nv_bfloat16 g_Wh[4][(size_t)D_MODEL * D_MODEL];  // W^T hi
__device__ __nv_bfloat16 g_Wl[4][(size_t)D_MODEL * D_MODEL];  // W^T lo
__device__ float g_VK[BATCH * NHEADS * 65 * 64];
__device__ float g_cos[SEQ * 32];
__device__ float g_sin[SEQ * 32];

// ---------------------------------------------------------------------------
// Portable (non-'a') PTX helpers: ldmatrix / mma.sync / cp.async
// ---------------------------------------------------------------------------
__device__ __forceinline__ uint32_t smem_u32(const void* p) {
    uint32_t a;
    asm("{ .reg .u64 t; cvta.to.shared.u64 t, %1; cvt.u32.u64 %0, t; }"
        : "=r"(a) : "l"(p));
    return a;
}

__device__ __forceinline__ void ldsm_x4(uint32_t addr, uint32_t* r) {
    asm volatile("ldmatrix.sync.aligned.m8n8.x4.shared.b16 {%0,%1,%2,%3}, [%4];"
                 : "=r"(r[0]), "=r"(r[1]), "=r"(r[2]), "=r"(r[3]) : "r"(addr));
}

__device__ __forceinline__ void mma_bf16(float* d, const uint32_t* a, const uint32_t* b) {
    asm volatile(
        "mma.sync.aligned.m16n8k16.row.col.f32.bf16.bf16.f32 "
        "{%0,%1,%2,%3}, {%4,%5,%6,%7}, {%8,%9}, {%0,%1,%2,%3};"
        : "+f"(d[0]), "+f"(d[1]), "+f"(d[2]), "+f"(d[3])
        : "r"(a[0]), "r"(a[1]), "r"(a[2]), "r"(a[3]), "r"(b[0]), "r"(b[1]));
}

__device__ __forceinline__ void cp_async16(uint32_t sdst, const void* gsrc) {
    asm volatile("cp.async.cg.shared.global [%0], [%1], 16;"
                 :: "r"(sdst), "l"(gsrc));
}
#define CP_COMMIT() asm volatile("cp.async.commit_group;")
#define CP_WAIT0()  asm volatile("cp.async.wait_group 0;" ::: "memory")

// ---------------------------------------------------------------------------
// RoPE table (fp64 once)
// ---------------------------------------------------------------------------
__global__ void rope_table_kernel() {
    int idx = blockIdx.x * blockDim.x + threadIdx.x;
    if (idx >= SEQ * 32) return;
    int s = idx >> 5;
    int p = idx & 31;
    double freq = exp(-((double)(2 * p) / 64.0) * 9.210340371976184);
    double ang = (double)s * freq;
    g_cos[idx] = (float)cos(ang);
    g_sin[idx] = (float)sin(ang);
}

// ---------------------------------------------------------------------------
// hi/lo bf16 split
// ---------------------------------------------------------------------------
__device__ __forceinline__ void split_bf16(float v, __nv_bfloat16& h, __nv_bfloat16& l) {
    h = __float2bfloat16(v);
    l = __float2bfloat16(v - __bfloat162float(h));
}

__global__ __launch_bounds__(256)
void convx_kernel(const float* __restrict__ x) {
    size_t i = ((size_t)blockIdx.x * 256 + threadIdx.x) * 4;
    if (i >= (size_t)MROWS * D_MODEL) return;
    float4 v = *(const float4*)(x + i);
    __nv_bfloat16 h[4], l[4];
    split_bf16(v.x, h[0], l[0]);
    split_bf16(v.y, h[1], l[1]);
    split_bf16(v.z, h[2], l[2]);
    split_bf16(v.w, h[3], l[3]);
    *(uint2*)(&g_Xh[i]) = *(uint2*)h;
    *(uint2*)(&g_Xl[i]) = *(uint2*)l;
}

// W[K,N] fp32 -> W^T[N,K] bf16 hi/lo
__global__ __launch_bounds__(256)
void wtrans_kernel(const float* __restrict__ W, __nv_bfloat16* __restrict__ Th,
                   __nv_bfloat16* __restrict__ Tl) {
    __shared__ float ts[32][33];
    int n0 = blockIdx.x * 32, k0 = blockIdx.y * 32;
    int tx = threadIdx.x & 31, ty = threadIdx.x >> 5;
    for (int i = ty; i < 32; i += 8)
        ts[i][tx] = W[(size_t)(k0 + i) * D_MODEL + n0 + tx];
    __syncthreads();
    for (int i = ty; i < 32; i += 8) {
        float v = ts[tx][i];
        __nv_bfloat16 h, l;
        split_bf16(v, h, l);
        size_t o = (size_t)(n0 + i) * D_MODEL + k0 + tx;
        Th[o] = h;
        Tl[o] = l;
    }
}

// ---------------------------------------------------------------------------
// Warp-MMA bf16 3-term GEMM: C[M,1024] = (Ah+Al) @ (Bh+Bl)^T
// CTA tile 128x128, BK=32, 8 warps (4m x 2n), warp tile 32x64.
// cp.async double-buffered SMEM; RoPE+ReLU fused in epilogue (ep=1).
// ---------------------------------------------------------------------------
#define GB_BM 128
#define GB_BN 128
#define GB_BK 32
#define ROWB 80                 // smem row stride in bytes (32 bf16 + 8 pad)
#define MAT_BYTES (128 * ROWB)  // 10240
#define AH_O 0
#define AL_O 10240
#define BH_O 20480
#define BL_O 30720
#define BUF_BYTES 40960
#define SMEM_GEMM (2 * BUF_BYTES)  // 81920

__global__ __launch_bounds__(256, 1)
void gemm_bf16x3(const __nv_bfloat16* __restrict__ Ah, const __nv_bfloat16* __restrict__ Al,
                 const __nv_bfloat16* __restrict__ Bh, const __nv_bfloat16* __restrict__ Bl,
                 float* __restrict__ C, int ep)
{
    extern __shared__ char smem[];
    const uint32_t sb = smem_u32(smem);
    const int tid = threadIdx.x;
    const int wid = tid >> 5;
    const int lane = tid & 31;
    const int wm = wid >> 1;        // 0..3: warp row  (32 rows each)
    const int wn = wid & 1;         // 0..1: warp col  (64 cols each)
    const int m0 = blockIdx.y * GB_BM;
    const int n0 = blockIdx.x * GB_BN;

    // Per-thread cp.async mapping: 2048 16B chunks / 256 threads = 8 each.
    // chunk = tid + q*256; mat = chunk>>9 (0:Ah 1:Al 2:Bh 3:Bl); id = chunk&511
    // row = id>>2 (0..127), c = id&3 (16B col chunk)
    const __nv_bfloat16* gsrc[4] = {
        Ah + (size_t)m0 * D_MODEL, Al + (size_t)m0 * D_MODEL,
        Bh + (size_t)n0 * D_MODEL, Bl + (size_t)n0 * D_MODEL
    };

    auto prefetch = [&](int it, int buf) {
        const int k0 = it * GB_BK;
        uint32_t bufb = sb + buf * BUF_BYTES;
#pragma unroll
        for (int q = 0; q < 8; q++) {
            int ch = tid + q * 256;
            int mat = ch >> 9;
            int id = ch & 511;
            int row = id >> 2, c = id & 3;
            const __nv_bfloat16* g = gsrc[mat] + (size_t)row * D_MODEL + k0 + c * 8;
            uint32_t sdst = bufb + mat * MAT_BYTES + row * ROWB + c * 16;
            cp_async16(sdst, g);
        }
        CP_COMMIT();
    };

    float acc[2][8][4];
#pragma unroll
    for (int t = 0; t < 2; t++)
#pragma unroll
        for (int j = 0; j < 8; j++)
#pragma unroll
            for (int e = 0; e < 4; e++) acc[t][j][e] = 0.0f;

    prefetch(0, 0);

    // ldmatrix address components (lane-invariant parts)
    const int a_row = wm * 32 + (lane & 15);
    const int a_colb = (lane >> 4) * 16;          // + s*32
    const int g = lane >> 3;
    const int b_row = wn * 64 + ((g >> 1) << 3) + (lane & 7);
    const int b_colb = (g & 1) * 16;              // + s*32

    const int NIT = D_MODEL / GB_BK;   // 32
    for (int it = 0; it < NIT; it++) {
        CP_WAIT0();
        __syncthreads();
        if (it + 1 < NIT) prefetch(it + 1, (it + 1) & 1);

        uint32_t bufb = sb + (it & 1) * BUF_BYTES;
#pragma unroll
        for (int s = 0; s < 2; s++) {
            uint32_t ah[2][4], al[2][4], bh[4][4], bl[4][4];
            uint32_t aaddr = bufb + a_row * ROWB + s * 32 + a_colb;
            ldsm_x4(aaddr + AH_O, ah[0]);
            ldsm_x4(aaddr + AH_O + 16 * ROWB, ah[1]);
            ldsm_x4(aaddr + AL_O, al[0]);
            ldsm_x4(aaddr + AL_O + 16 * ROWB, al[1]);
            uint32_t baddr = bufb + b_row * ROWB + s * 32 + b_colb;
#pragma unroll
            for (int j2 = 0; j2 < 4; j2++) {
                ldsm_x4(baddr + BH_O + j2 * 16 * ROWB, bh[j2]);
                ldsm_x4(baddr + BL_O + j2 * 16 * ROWB, bl[j2]);
            }
#pragma unroll
            for (int t = 0; t < 2; t++)
#pragma unroll
                for (int j = 0; j < 8; j++) {
                    const uint32_t* bhp = &bh[j >> 1][(j & 1) * 2];
                    const uint32_t* blp = &bl[j >> 1][(j & 1) * 2];
                    mma_bf16(acc[t][j], ah[t], bhp);
                    mma_bf16(acc[t][j], ah[t], blp);
                    mma_bf16(acc[t][j], al[t], bhp);
                }
        }
        __syncthreads();
    }

    // ---- epilogue on register accumulators ----
    // acc[t][j]: c0,c1 -> (row, col), (row, col+1); c2,c3 -> row+8
    // row = m0 + wm*32 + t*16 + lane/4 (+8), col = n0 + wn*64 + j*8 + 2*(lane%4)
#pragma unroll
    for (int t = 0; t < 2; t++) {
        int rbase = m0 + wm * 32 + t * 16 + (lane >> 2);
#pragma unroll
        for (int half = 0; half < 2; half++) {
            int row = rbase + half * 8;
            int s = row & (SEQ - 1);
#pragma unroll
            for (int j = 0; j < 8; j++) {
                int col = n0 + wn * 64 + j * 8 + (lane & 3) * 2;
                float x1 = acc[t][j][half * 2 + 0];
                float x2 = acc[t][j][half * 2 + 1];
                if (ep) {
                    int p = (col & 63) >> 1;
                    float cs = g_cos[s * 32 + p];
                    float sn = g_sin[s * 32 + p];
                    float r1 = x1 * cs - x2 * sn;
                    float r2 = fmaf(x1, sn, x2 * cs);
                    x1 = fmaxf(r1, 0.0f);
                    x2 = fmaxf(r2, 0.0f);
                }
                *(float2*)(C + (size_t)row * D_MODEL + col) = make_float2(x1, x2);
            }
        }
    }
}

// ---------------------------------------------------------------------------
// vk: zero + partial accumulation (512 CTAs) + atomicAdd
// ---------------------------------------------------------------------------
__global__ void zero_vk_kernel() {
    int i = blockIdx.x * 256 + threadIdx.x;
    if (i < BATCH * NHEADS * 65 * 64) g_VK[i] = 0.0f;
}

__global__ __launch_bounds__(256)
void vk_partial_kernel()
{
    __shared__ float ks[64][64];
    __shared__ float vs[64][64];

    const int bh = blockIdx.x;
    const int part = blockIdx.y;       // 0..7, 512 seq rows each
    const int b = bh >> 4;
    const int h = bh & 15;
    const int t = threadIdx.x;
    const int d  = t & 63;
    const int eg = t >> 6;

    const size_t base = (size_t)b * SEQ * D_MODEL + (size_t)h * 64;
    const int r0 = part * 512;

    float acc[16];
#pragma unroll
    for (int j = 0; j < 16; j++) acc[j] = 0.0f;
    float ksum = 0.0f;

    for (int c = 0; c < 8; c++) {
        for (int i = t; i < 64 * 64; i += 256) {
            int row = i >> 6, col = i & 63;
            size_t goff = base + (size_t)(r0 + c * 64 + row) * D_MODEL + col;
            ks[row][col] = g_K[goff];
            vs[row][col] = g_V[goff];
        }
        __syncthreads();
#pragma unroll 4
        for (int ss = 0; ss < 64; ss++) {
            float kv = ks[ss][d];
            if (eg == 0) ksum += kv;
#pragma unroll
            for (int j = 0; j < 16; j++)
                acc[j] = fmaf(vs[ss][eg * 16 + j], kv, acc[j]);
        }
        __syncthreads();
    }

    float* vkp = g_VK + (size_t)bh * 65 * 64;
#pragma unroll
    for (int j = 0; j < 16; j++)
        atomicAdd(&vkp[(eg * 16 + j) * 64 + d], acc[j]);
    if (eg == 0)
        atomicAdd(&vkp[64 * 64 + d], ksum);
}

// ---------------------------------------------------------------------------
// attn: writes bf16 hi/lo directly (feeds final tensor-core GEMM)
// ---------------------------------------------------------------------------
__global__ __launch_bounds__(256)
void attn_kernel()
{
    __shared__ float vkS[65][64];
    const int bh = blockIdx.x;
    const int b = bh >> 4;
    const int h = bh & 15;
    const int t = threadIdx.x;

    const float* vkp = g_VK + (size_t)bh * 65 * 64;
    for (int i = t; i < 65 * 64; i += 256)
        vkS[i >> 6][i & 63] = vkp[i];
    __syncthreads();

    const int l = blockIdx.y * 256 + t;
    const size_t roff = ((size_t)(b * SEQ + l)) * D_MODEL + (size_t)h * 64;
    const float* qr = g_Q + roff;

    float q[64];
#pragma unroll
    for (int i = 0; i < 16; i++) {
        float4 v4 = ((const float4*)qr)[i];
        q[4 * i + 0] = v4.x; q[4 * i + 1] = v4.y;
        q[4 * i + 2] = v4.z; q[4 * i + 3] = v4.w;
    }

    float denom = 1e-6f;
#pragma unroll
    for (int d = 0; d < 64; d++) denom = fmaf(vkS[64][d], q[d], denom);
    float inv = 1.0f / denom;

    __nv_bfloat16 oh[64], ol[64];
    for (int e = 0; e < 64; e++) {
        float num = 0.0f;
#pragma unroll
        for (int d = 0; d < 64; d++) num = fmaf(vkS[e][d], q[d], num);
        split_bf16(num * inv, oh[e], ol[e]);
    }
#pragma unroll
    for (int i = 0; i < 8; i++) {
        ((uint4*)(g_Ah + roff))[i] = ((uint4*)oh)[i];
        ((uint4*)(g_Al + roff))[i] = ((uint4*)ol)[i];
    }
}

// ---------------------------------------------------------------------------
// kernel_launch
// ---------------------------------------------------------------------------
extern "C" void kernel_launch(void* const* d_in, const int* in_sizes, int n_in,
                              void* d_out, int out_size)
{
    const float* x  = (const float*)d_in[0];
    const float* Wq = (const float*)d_in[1];
    const float* Wk = (const float*)d_in[2];
    const float* Wv = (const float*)d_in[3];
    const float* Wo = (const float*)d_in[4];
    float* out = (float*)d_out;

    float *qp, *kp, *vp;
    __nv_bfloat16 *xh, *xl, *ah, *al, *wh, *wl;
    cudaGetSymbolAddress((void**)&qp, g_Q);
    cudaGetSymbolAddress((void**)&kp, g_K);
    cudaGetSymbolAddress((void**)&vp, g_V);
    cudaGetSymbolAddress((void**)&xh, g_Xh);
    cudaGetSymbolAddress((void**)&xl, g_Xl);
    cudaGetSymbolAddress((void**)&ah, g_Ah);
    cudaGetSymbolAddress((void**)&al, g_Al);
    cudaGetSymbolAddress((void**)&wh, g_Wh);
    cudaGetSymbolAddress((void**)&wl, g_Wl);
    const size_t WSZ = (size_t)D_MODEL * D_MODEL;

    cudaFuncSetAttribute(gemm_bf16x3, cudaFuncAttributeMaxDynamicSharedMemorySize, SMEM_GEMM);

    rope_table_kernel<<<(SEQ * 32 + 255) / 256, 256>>>();
    convx_kernel<<<(MROWS * D_MODEL / 4 + 255) / 256, 256>>>(x);

    dim3 tgrid(D_MODEL / 32, D_MODEL / 32);
    wtrans_kernel<<<tgrid, 256>>>(Wq, wh + 0 * WSZ, wl + 0 * WSZ);
    wtrans_kernel<<<tgrid, 256>>>(Wk, wh + 1 * WSZ, wl + 1 * WSZ);
    wtrans_kernel<<<tgrid, 256>>>(Wv, wh + 2 * WSZ, wl + 2 * WSZ);
    wtrans_kernel<<<tgrid, 256>>>(Wo, wh + 3 * WSZ, wl + 3 * WSZ);

    dim3 ggrid(D_MODEL / GB_BN, MROWS / GB_BM);   // (8, 128)
    gemm_bf16x3<<<ggrid, 256, SMEM_GEMM>>>(xh, xl, wh + 0 * WSZ, wl + 0 * WSZ, qp, 1);
    gemm_bf16x3<<<ggrid, 256, SMEM_GEMM>>>(xh, xl, wh + 1 * WSZ, wl + 1 * WSZ, kp, 1);
    gemm_bf16x3<<<ggrid, 256, SMEM_GEMM>>>(xh, xl, wh + 2 * WSZ, wl + 2 * WSZ, vp, 0);

    zero_vk_kernel<<<(BATCH * NHEADS * 65 * 64 + 255) / 256, 256>>>();
    vk_partial_kernel<<<dim3(BATCH * NHEADS, 8), 256>>>();
    attn_kernel<<<dim3(BATCH * NHEADS, SEQ / 256), 256>>>();

    gemm_bf16x3<<<ggrid, 256, SMEM_GEMM>>>(ah, al, wh + 3 * WSZ, wl + 3 * WSZ, out, 0);
}

// round 16
// speedup vs baseline: 2.2511x; 1.0027x over previous
#include <cuda_runtime.h>
#include <cuda_bf16.h>
#include <math.h>
#include <stdint.h>

#define D_MODEL 1024
#define NHEADS  16
#define SEQ     4096
#define BATCH   4
#define MROWS   (BATCH * SEQ)   // 16384

// ---------------------------------------------------------------------------
// Scratch (device globals: allocation-free per harness rules)
// ---------------------------------------------------------------------------
__device__ float g_Q[(size_t)MROWS * D_MODEL];
__device__ float g_K[(size_t)MROWS * D_MODEL];
__device__ float g_V[(size_t)MROWS * D_MODEL];
__device__ __nv_bfloat16 g_Xh[(size_t)MROWS * D_MODEL];
__device__ __nv_bfloat16 g_Xl[(size_t)MROWS * D_MODEL];
__device__ __nv_bfloat16 g_Ah[(size_t)MROWS * D_MODEL];
__device__ __nv_bfloat16 g_Al[(size_t)MROWS * D_MODEL];
__device__ __nv_bfloat16 g_Wh[4][(size_t)D_MODEL * D_MODEL];  // W^T hi
__device__ __nv_bfloat16 g_Wl[4][(size_t)D_MODEL * D_MODEL];  // W^T lo
__device__ float g_VK[BATCH * NHEADS * 65 * 64];
__device__ float g_cos[SEQ * 32];
__device__ float g_sin[SEQ * 32];

// ---------------------------------------------------------------------------
// Portable (non-'a') PTX helpers: ldmatrix / mma.sync / cp.async
// ---------------------------------------------------------------------------
__device__ __forceinline__ uint32_t smem_u32(const void* p) {
    uint32_t a;
    asm("{ .reg .u64 t; cvta.to.shared.u64 t, %1; cvt.u32.u64 %0, t; }"
        : "=r"(a) : "l"(p));
    return a;
}

__device__ __forceinline__ void ldsm_x4(uint32_t addr, uint32_t* r) {
    asm volatile("ldmatrix.sync.aligned.m8n8.x4.shared.b16 {%0,%1,%2,%3}, [%4];"
                 : "=r"(r[0]), "=r"(r[1]), "=r"(r[2]), "=r"(r[3]) : "r"(addr));
}

__device__ __forceinline__ void mma_bf16(float* d, const uint32_t* a, const uint32_t* b) {
    asm volatile(
        "mma.sync.aligned.m16n8k16.row.col.f32.bf16.bf16.f32 "
        "{%0,%1,%2,%3}, {%4,%5,%6,%7}, {%8,%9}, {%0,%1,%2,%3};"
        : "+f"(d[0]), "+f"(d[1]), "+f"(d[2]), "+f"(d[3])
        : "r"(a[0]), "r"(a[1]), "r"(a[2]), "r"(a[3]), "r"(b[0]), "r"(b[1]));
}

__device__ __forceinline__ void cp_async16(uint32_t sdst, const void* gsrc) {
    asm volatile("cp.async.cg.shared.global [%0], [%1], 16;"
                 :: "r"(sdst), "l"(gsrc));
}
#define CP_COMMIT() asm volatile("cp.async.commit_group;")
#define CP_WAIT1()  asm volatile("cp.async.wait_group 1;" ::: "memory")
#define CP_WAIT0()  asm volatile("cp.async.wait_group 0;" ::: "memory")

// ---------------------------------------------------------------------------
// RoPE table (fp64 once)
// ---------------------------------------------------------------------------
__global__ void rope_table_kernel() {
    int idx = blockIdx.x * blockDim.x + threadIdx.x;
    if (idx >= SEQ * 32) return;
    int s = idx >> 5;
    int p = idx & 31;
    double freq = exp(-((double)(2 * p) / 64.0) * 9.210340371976184);
    double ang = (double)s * freq;
    g_cos[idx] = (float)cos(ang);
    g_sin[idx] = (float)sin(ang);
}

// ---------------------------------------------------------------------------
// hi/lo bf16 split
// ---------------------------------------------------------------------------
__device__ __forceinline__ void split_bf16(float v, __nv_bfloat16& h, __nv_bfloat16& l) {
    h = __float2bfloat16(v);
    l = __float2bfloat16(v - __bfloat162float(h));
}

__global__ __launch_bounds__(256)
void convx_kernel(const float* __restrict__ x) {
    size_t i = ((size_t)blockIdx.x * 256 + threadIdx.x) * 4;
    if (i >= (size_t)MROWS * D_MODEL) return;
    float4 v = *(const float4*)(x + i);
    __nv_bfloat16 h[4], l[4];
    split_bf16(v.x, h[0], l[0]);
    split_bf16(v.y, h[1], l[1]);
    split_bf16(v.z, h[2], l[2]);
    split_bf16(v.w, h[3], l[3]);
    *(uint2*)(&g_Xh[i]) = *(uint2*)h;
    *(uint2*)(&g_Xl[i]) = *(uint2*)l;
}

// W[K,N] fp32 -> W^T[N,K] bf16 hi/lo
__global__ __launch_bounds__(256)
void wtrans_kernel(const float* __restrict__ W, __nv_bfloat16* __restrict__ Th,
                   __nv_bfloat16* __restrict__ Tl) {
    __shared__ float ts[32][33];
    int n0 = blockIdx.x * 32, k0 = blockIdx.y * 32;
    int tx = threadIdx.x & 31, ty = threadIdx.x >> 5;
    for (int i = ty; i < 32; i += 8)
        ts[i][tx] = W[(size_t)(k0 + i) * D_MODEL + n0 + tx];
    __syncthreads();
    for (int i = ty; i < 32; i += 8) {
        float v = ts[tx][i];
        __nv_bfloat16 h, l;
        split_bf16(v, h, l);
        size_t o = (size_t)(n0 + i) * D_MODEL + k0 + tx;
        Th[o] = h;
        Tl[o] = l;
    }
}

// ---------------------------------------------------------------------------
// Warp-MMA bf16 3-term GEMM: C[M,1024] = (Ah+Al) @ (Bh+Bl)^T
// CTA tile 128x128, BK=32, 8 warps (4m x 2n), warp tile 32x64.
// 3-stage cp.async pipeline (2 groups in flight, wait_group 1,
// single __syncthreads per K-iteration). RoPE+ReLU fused (ep=1).
// ---------------------------------------------------------------------------
#define GB_BM 128
#define GB_BN 128
#define GB_BK 32
#define ROWB 80                 // smem row stride in bytes (32 bf16 + 8 pad)
#define MAT_BYTES (128 * ROWB)  // 10240
#define AH_O 0
#define AL_O 10240
#define BH_O 20480
#define BL_O 30720
#define BUF_BYTES 40960
#define NSTAGE 3
#define SMEM_GEMM (NSTAGE * BUF_BYTES)  // 122880

__global__ __launch_bounds__(256, 1)
void gemm_bf16x3(const __nv_bfloat16* __restrict__ Ah, const __nv_bfloat16* __restrict__ Al,
                 const __nv_bfloat16* __restrict__ Bh, const __nv_bfloat16* __restrict__ Bl,
                 float* __restrict__ C, int ep)
{
    extern __shared__ char smem[];
    const uint32_t sb = smem_u32(smem);
    const int tid = threadIdx.x;
    const int wid = tid >> 5;
    const int lane = tid & 31;
    const int wm = wid >> 1;        // 0..3: warp row  (32 rows each)
    const int wn = wid & 1;         // 0..1: warp col  (64 cols each)
    const int m0 = blockIdx.y * GB_BM;
    const int n0 = blockIdx.x * GB_BN;

    // Per-thread cp.async mapping: 2048 16B chunks / 256 threads = 8 each.
    const __nv_bfloat16* gsrc[4] = {
        Ah + (size_t)m0 * D_MODEL, Al + (size_t)m0 * D_MODEL,
        Bh + (size_t)n0 * D_MODEL, Bl + (size_t)n0 * D_MODEL
    };

    auto prefetch = [&](int it, int buf) {
        const int k0 = it * GB_BK;
        uint32_t bufb = sb + buf * BUF_BYTES;
#pragma unroll
        for (int q = 0; q < 8; q++) {
            int ch = tid + q * 256;
            int mat = ch >> 9;
            int id = ch & 511;
            int row = id >> 2, c = id & 3;
            const __nv_bfloat16* g = gsrc[mat] + (size_t)row * D_MODEL + k0 + c * 8;
            uint32_t sdst = bufb + mat * MAT_BYTES + row * ROWB + c * 16;
            cp_async16(sdst, g);
        }
        CP_COMMIT();
    };

    float acc[2][8][4];
#pragma unroll
    for (int t = 0; t < 2; t++)
#pragma unroll
        for (int j = 0; j < 8; j++)
#pragma unroll
            for (int e = 0; e < 4; e++) acc[t][j][e] = 0.0f;

    // ldmatrix address components (lane-invariant parts)
    const int a_row = wm * 32 + (lane & 15);
    const int a_colb = (lane >> 4) * 16;          // + s*32
    const int g = lane >> 3;
    const int b_row = wn * 64 + ((g >> 1) << 3) + (lane & 7);
    const int b_colb = (g & 1) * 16;              // + s*32

    const int NIT = D_MODEL / GB_BK;   // 32

    prefetch(0, 0);
    prefetch(1, 1);

    int buf = 0;
    for (int it = 0; it < NIT; it++) {
        CP_WAIT1();                 // oldest group (stage it) complete
        __syncthreads();            // also: stage it-1 compute done by all warps
        if (it + 2 < NIT) {
            int nb = buf + 2; if (nb >= NSTAGE) nb -= NSTAGE;
            prefetch(it + 2, nb);
        } else {
            CP_COMMIT();            // empty group keeps wait_group arithmetic valid
        }

        uint32_t bufb = sb + buf * BUF_BYTES;
#pragma unroll
        for (int s = 0; s < 2; s++) {
            uint32_t ah[2][4], al[2][4], bh[4][4], bl[4][4];
            uint32_t aaddr = bufb + a_row * ROWB + s * 32 + a_colb;
            ldsm_x4(aaddr + AH_O, ah[0]);
            ldsm_x4(aaddr + AH_O + 16 * ROWB, ah[1]);
            ldsm_x4(aaddr + AL_O, al[0]);
            ldsm_x4(aaddr + AL_O + 16 * ROWB, al[1]);
            uint32_t baddr = bufb + b_row * ROWB + s * 32 + b_colb;
#pragma unroll
            for (int j2 = 0; j2 < 4; j2++) {
                ldsm_x4(baddr + BH_O + j2 * 16 * ROWB, bh[j2]);
                ldsm_x4(baddr + BL_O + j2 * 16 * ROWB, bl[j2]);
            }
#pragma unroll
            for (int t = 0; t < 2; t++)
#pragma unroll
                for (int j = 0; j < 8; j++) {
                    const uint32_t* bhp = &bh[j >> 1][(j & 1) * 2];
                    const uint32_t* blp = &bl[j >> 1][(j & 1) * 2];
                    mma_bf16(acc[t][j], ah[t], bhp);
                    mma_bf16(acc[t][j], ah[t], blp);
                    mma_bf16(acc[t][j], al[t], bhp);
                }
        }
        buf++; if (buf >= NSTAGE) buf = 0;
    }

    // ---- epilogue on register accumulators ----
#pragma unroll
    for (int t = 0; t < 2; t++) {
        int rbase = m0 + wm * 32 + t * 16 + (lane >> 2);
#pragma unroll
        for (int half = 0; half < 2; half++) {
            int row = rbase + half * 8;
            int s = row & (SEQ - 1);
#pragma unroll
            for (int j = 0; j < 8; j++) {
                int col = n0 + wn * 64 + j * 8 + (lane & 3) * 2;
                float x1 = acc[t][j][half * 2 + 0];
                float x2 = acc[t][j][half * 2 + 1];
                if (ep) {
                    int p = (col & 63) >> 1;
                    float cs = g_cos[s * 32 + p];
                    float sn = g_sin[s * 32 + p];
                    float r1 = x1 * cs - x2 * sn;
                    float r2 = fmaf(x1, sn, x2 * cs);
                    x1 = fmaxf(r1, 0.0f);
                    x2 = fmaxf(r2, 0.0f);
                }
                *(float2*)(C + (size_t)row * D_MODEL + col) = make_float2(x1, x2);
            }
        }
    }
}

// ---------------------------------------------------------------------------
// vk: zero + partial accumulation (512 CTAs) + atomicAdd
// ---------------------------------------------------------------------------
__global__ void zero_vk_kernel() {
    int i = blockIdx.x * 256 + threadIdx.x;
    if (i < BATCH * NHEADS * 65 * 64) g_VK[i] = 0.0f;
}

__global__ __launch_bounds__(256)
void vk_partial_kernel()
{
    __shared__ float ks[64][64];
    __shared__ float vs[64][64];

    const int bh = blockIdx.x;
    const int part = blockIdx.y;       // 0..7, 512 seq rows each
    const int b = bh >> 4;
    const int h = bh & 15;
    const int t = threadIdx.x;
    const int d  = t & 63;
    const int eg = t >> 6;

    const size_t base = (size_t)b * SEQ * D_MODEL + (size_t)h * 64;
    const int r0 = part * 512;

    float acc[16];
#pragma unroll
    for (int j = 0; j < 16; j++) acc[j] = 0.0f;
    float ksum = 0.0f;

    for (int c = 0; c < 8; c++) {
        for (int i = t; i < 64 * 64; i += 256) {
            int row = i >> 6, col = i & 63;
            size_t goff = base + (size_t)(r0 + c * 64 + row) * D_MODEL + col;
            ks[row][col] = g_K[goff];
            vs[row][col] = g_V[goff];
        }
        __syncthreads();
#pragma unroll 4
        for (int ss = 0; ss < 64; ss++) {
            float kv = ks[ss][d];
            if (eg == 0) ksum += kv;
#pragma unroll
            for (int j = 0; j < 16; j++)
                acc[j] = fmaf(vs[ss][eg * 16 + j], kv, acc[j]);
        }
        __syncthreads();
    }

    float* vkp = g_VK + (size_t)bh * 65 * 64;
#pragma unroll
    for (int j = 0; j < 16; j++)
        atomicAdd(&vkp[(eg * 16 + j) * 64 + d], acc[j]);
    if (eg == 0)
        atomicAdd(&vkp[64 * 64 + d], ksum);
}

// ---------------------------------------------------------------------------
// attn: writes bf16 hi/lo directly (feeds final tensor-core GEMM)
// ---------------------------------------------------------------------------
__global__ __launch_bounds__(256)
void attn_kernel()
{
    __shared__ float vkS[65][64];
    const int bh = blockIdx.x;
    const int b = bh >> 4;
    const int h = bh & 15;
    const int t = threadIdx.x;

    const float* vkp = g_VK + (size_t)bh * 65 * 64;
    for (int i = t; i < 65 * 64; i += 256)
        vkS[i >> 6][i & 63] = vkp[i];
    __syncthreads();

    const int l = blockIdx.y * 256 + t;
    const size_t roff = ((size_t)(b * SEQ + l)) * D_MODEL + (size_t)h * 64;
    const float* qr = g_Q + roff;

    float q[64];
#pragma unroll
    for (int i = 0; i < 16; i++) {
        float4 v4 = ((const float4*)qr)[i];
        q[4 * i + 0] = v4.x; q[4 * i + 1] = v4.y;
        q[4 * i + 2] = v4.z; q[4 * i + 3] = v4.w;
    }

    float denom = 1e-6f;
#pragma unroll
    for (int d = 0; d < 64; d++) denom = fmaf(vkS[64][d], q[d], denom);
    float inv = 1.0f / denom;

    __nv_bfloat16 oh[64], ol[64];
    for (int e = 0; e < 64; e++) {
        float num = 0.0f;
#pragma unroll
        for (int d = 0; d < 64; d++) num = fmaf(vkS[e][d], q[d], num);
        split_bf16(num * inv, oh[e], ol[e]);
    }
#pragma unroll
    for (int i = 0; i < 8; i++) {
        ((uint4*)(g_Ah + roff))[i] = ((uint4*)oh)[i];
        ((uint4*)(g_Al + roff))[i] = ((uint4*)ol)[i];
    }
}

// ---------------------------------------------------------------------------
// kernel_launch
// ---------------------------------------------------------------------------
extern "C" void kernel_launch(void* const* d_in, const int* in_sizes, int n_in,
                              void* d_out, int out_size)
{
    const float* x  = (const float*)d_in[0];
    const float* Wq = (const float*)d_in[1];
    const float* Wk = (const float*)d_in[2];
    const float* Wv = (const float*)d_in[3];
    const float* Wo = (const float*)d_in[4];
    float* out = (float*)d_out;

    float *qp, *kp, *vp;
    __nv_bfloat16 *xh, *xl, *ah, *al, *wh, *wl;
    cudaGetSymbolAddress((void**)&qp, g_Q);
    cudaGetSymbolAddress((void**)&kp, g_K);
    cudaGetSymbolAddress((void**)&vp, g_V);
    cudaGetSymbolAddress((void**)&xh, g_Xh);
    cudaGetSymbolAddress((void**)&xl, g_Xl);
    cudaGetSymbolAddress((void**)&ah, g_Ah);
    cudaGetSymbolAddress((void**)&al, g_Al);
    cudaGetSymbolAddress((void**)&wh, g_Wh);
    cudaGetSymbolAddress((void**)&wl, g_Wl);
    const size_t WSZ = (size_t)D_MODEL * D_MODEL;

    cudaFuncSetAttribute(gemm_bf16x3, cudaFuncAttributeMaxDynamicSharedMemorySize, SMEM_GEMM);

    rope_table_kernel<<<(SEQ * 32 + 255) / 256, 256>>>();
    convx_kernel<<<(MROWS * D_MODEL / 4 + 255) / 256, 256>>>(x);

    dim3 tgrid(D_MODEL / 32, D_MODEL / 32);
    wtrans_kernel<<<tgrid, 256>>>(Wq, wh + 0 * WSZ, wl + 0 * WSZ);
    wtrans_kernel<<<tgrid, 256>>>(Wk, wh + 1 * WSZ, wl + 1 * WSZ);
    wtrans_kernel<<<tgrid, 256>>>(Wv, wh + 2 * WSZ, wl + 2 * WSZ);
    wtrans_kernel<<<tgrid, 256>>>(Wo, wh + 3 * WSZ, wl + 3 * WSZ);

    dim3 ggrid(D_MODEL / GB_BN, MROWS / GB_BM);   // (8, 128)
    gemm_bf16x3<<<ggrid, 256, SMEM_GEMM>>>(xh, xl, wh + 0 * WSZ, wl + 0 * WSZ, qp, 1);
    gemm_bf16x3<<<ggrid, 256, SMEM_GEMM>>>(xh, xl, wh + 1 * WSZ, wl + 1 * WSZ, kp, 1);
    gemm_bf16x3<<<ggrid, 256, SMEM_GEMM>>>(xh, xl, wh + 2 * WSZ, wl + 2 * WSZ, vp, 0);

    zero_vk_kernel<<<(BATCH * NHEADS * 65 * 64 + 255) / 256, 256>>>();
    vk_partial_kernel<<<dim3(BATCH * NHEADS, 8), 256>>>();
    attn_kernel<<<dim3(BATCH * NHEADS, SEQ / 256), 256>>>();

    gemm_bf16x3<<<ggrid, 256, SMEM_GEMM>>>(ah, al, wh + 3 * WSZ, wl + 3 * WSZ, out, 0);
}

// round 17
// speedup vs baseline: 2.9118x; 1.2935x over previous
#include <cuda_runtime.h>
#include <cuda_fp16.h>
#include <math.h>
#include <stdint.h>

#define D_MODEL 1024
#define NHEADS  16
#define SEQ     4096
#define BATCH   4
#define MROWS   (BATCH * SEQ)   // 16384

// ---------------------------------------------------------------------------
// Scratch (device globals: allocation-free per harness rules)
// ---------------------------------------------------------------------------
__device__ float g_Q[(size_t)MROWS * D_MODEL];
__device__ float g_K[(size_t)MROWS * D_MODEL];
__device__ float g_V[(size_t)MROWS * D_MODEL];
__device__ __half g_Xh[(size_t)MROWS * D_MODEL];              // x, fp16
__device__ __half g_Ah[(size_t)MROWS * D_MODEL];              // attn out, fp16
__device__ __half g_Wh[4][(size_t)D_MODEL * D_MODEL];         // W^T hi
__device__ __half g_Wl[4][(size_t)D_MODEL * D_MODEL];         // W^T lo
__device__ float g_VK[BATCH * NHEADS * 65 * 64];
__device__ float g_cos[SEQ * 32];
__device__ float g_sin[SEQ * 32];

// ---------------------------------------------------------------------------
// Portable (non-'a') PTX helpers: ldmatrix / mma.sync / cp.async
// ---------------------------------------------------------------------------
__device__ __forceinline__ uint32_t smem_u32(const void* p) {
    uint32_t a;
    asm("{ .reg .u64 t; cvta.to.shared.u64 t, %1; cvt.u32.u64 %0, t; }"
        : "=r"(a) : "l"(p));
    return a;
}

__device__ __forceinline__ void ldsm_x4(uint32_t addr, uint32_t* r) {
    asm volatile("ldmatrix.sync.aligned.m8n8.x4.shared.b16 {%0,%1,%2,%3}, [%4];"
                 : "=r"(r[0]), "=r"(r[1]), "=r"(r[2]), "=r"(r[3]) : "r"(addr));
}

__device__ __forceinline__ void mma_fp16(float* d, const uint32_t* a, const uint32_t* b) {
    asm volatile(
        "mma.sync.aligned.m16n8k16.row.col.f32.f16.f16.f32 "
        "{%0,%1,%2,%3}, {%4,%5,%6,%7}, {%8,%9}, {%0,%1,%2,%3};"
        : "+f"(d[0]), "+f"(d[1]), "+f"(d[2]), "+f"(d[3])
        : "r"(a[0]), "r"(a[1]), "r"(a[2]), "r"(a[3]), "r"(b[0]), "r"(b[1]));
}

__device__ __forceinline__ void cp_async16(uint32_t sdst, const void* gsrc) {
    asm volatile("cp.async.cg.shared.global [%0], [%1], 16;"
                 :: "r"(sdst), "l"(gsrc));
}
#define CP_COMMIT() asm volatile("cp.async.commit_group;")
#define CP_WAIT2()  asm volatile("cp.async.wait_group 2;" ::: "memory")

// ---------------------------------------------------------------------------
// RoPE table (fp64 once)
// ---------------------------------------------------------------------------
__global__ void rope_table_kernel() {
    int idx = blockIdx.x * blockDim.x + threadIdx.x;
    if (idx >= SEQ * 32) return;
    int s = idx >> 5;
    int p = idx & 31;
    double freq = exp(-((double)(2 * p) / 64.0) * 9.210340371976184);
    double ang = (double)s * freq;
    g_cos[idx] = (float)cos(ang);
    g_sin[idx] = (float)sin(ang);
}

// ---------------------------------------------------------------------------
// fp16 hi/lo split (lo only needed for weights)
// ---------------------------------------------------------------------------
__device__ __forceinline__ void split_h(float v, __half& h, __half& l) {
    h = __float2half_rn(v);
    l = __float2half_rn(v - __half2float(h));
}

// x -> Xh (single fp16 rounding)
__global__ __launch_bounds__(256)
void convx_kernel(const float* __restrict__ x) {
    size_t i = ((size_t)blockIdx.x * 256 + threadIdx.x) * 4;
    if (i >= (size_t)MROWS * D_MODEL) return;
    float4 v = *(const float4*)(x + i);
    __half h[4];
    h[0] = __float2half_rn(v.x);
    h[1] = __float2half_rn(v.y);
    h[2] = __float2half_rn(v.z);
    h[3] = __float2half_rn(v.w);
    *(uint2*)(&g_Xh[i]) = *(uint2*)h;
}

// W[K,N] fp32 -> W^T[N,K] fp16 hi/lo
__global__ __launch_bounds__(256)
void wtrans_kernel(const float* __restrict__ W, __half* __restrict__ Th,
                   __half* __restrict__ Tl) {
    __shared__ float ts[32][33];
    int n0 = blockIdx.x * 32, k0 = blockIdx.y * 32;
    int tx = threadIdx.x & 31, ty = threadIdx.x >> 5;
    for (int i = ty; i < 32; i += 8)
        ts[i][tx] = W[(size_t)(k0 + i) * D_MODEL + n0 + tx];
    __syncthreads();
    for (int i = ty; i < 32; i += 8) {
        float v = ts[tx][i];
        __half h, l;
        split_h(v, h, l);
        size_t o = (size_t)(n0 + i) * D_MODEL + k0 + tx;
        Th[o] = h;
        Tl[o] = l;
    }
}

// ---------------------------------------------------------------------------
// Warp-MMA fp16 2-term GEMM: C[M,1024] = Ah @ (Bh+Bl)^T
// CTA tile 128x128, BK=32, 8 warps (4m x 2n), warp tile 32x64.
// 4-stage cp.async pipeline (3 groups in flight, wait_group 2).
// RoPE+ReLU fused in epilogue (ep=1).
// ---------------------------------------------------------------------------
#define GB_BM 128
#define GB_BN 128
#define GB_BK 32
#define ROWB 80                 // smem row stride in bytes (32 fp16 + 8 pad)
#define MAT_BYTES (128 * ROWB)  // 10240
#define AH_O 0
#define BH_O 10240
#define BL_O 20480
#define BUF_BYTES 30720
#define NSTAGE 4
#define SMEM_GEMM (NSTAGE * BUF_BYTES)  // 122880

__global__ __launch_bounds__(256, 1)
void gemm_fp16x2(const __half* __restrict__ Ah,
                 const __half* __restrict__ Bh, const __half* __restrict__ Bl,
                 float* __restrict__ C, int ep)
{
    extern __shared__ char smem[];
    const uint32_t sb = smem_u32(smem);
    const int tid = threadIdx.x;
    const int wid = tid >> 5;
    const int lane = tid & 31;
    const int wm = wid >> 1;        // 0..3: warp row  (32 rows each)
    const int wn = wid & 1;         // 0..1: warp col  (64 cols each)
    const int m0 = blockIdx.y * GB_BM;
    const int n0 = blockIdx.x * GB_BN;

    // cp.async mapping: 1536 16B chunks / 256 threads = 6 each.
    // chunk = tid + q*256; mat = chunk>>9 (0:Ah 1:Bh 2:Bl); id = chunk&511
    // row = id>>2 (0..127), c = id&3 (16B col chunk)
    const __half* gsrc[3] = {
        Ah + (size_t)m0 * D_MODEL,
        Bh + (size_t)n0 * D_MODEL,
        Bl + (size_t)n0 * D_MODEL
    };

    auto prefetch = [&](int it, int buf) {
        const int k0 = it * GB_BK;
        uint32_t bufb = sb + buf * BUF_BYTES;
#pragma unroll
        for (int q = 0; q < 6; q++) {
            int ch = tid + q * 256;
            int mat = ch >> 9;
            int id = ch & 511;
            int row = id >> 2, c = id & 3;
            const __half* g = gsrc[mat] + (size_t)row * D_MODEL + k0 + c * 8;
            uint32_t sdst = bufb + mat * MAT_BYTES + row * ROWB + c * 16;
            cp_async16(sdst, g);
        }
        CP_COMMIT();
    };

    float acc[2][8][4];
#pragma unroll
    for (int t = 0; t < 2; t++)
#pragma unroll
        for (int j = 0; j < 8; j++)
#pragma unroll
            for (int e = 0; e < 4; e++) acc[t][j][e] = 0.0f;

    // ldmatrix address components
    const int a_row = wm * 32 + (lane & 15);
    const int a_colb = (lane >> 4) * 16;          // + s*32
    const int g = lane >> 3;
    const int b_row = wn * 64 + ((g >> 1) << 3) + (lane & 7);
    const int b_colb = (g & 1) * 16;              // + s*32

    const int NIT = D_MODEL / GB_BK;   // 32

    prefetch(0, 0);
    prefetch(1, 1);
    prefetch(2, 2);

    int buf = 0;
    for (int it = 0; it < NIT; it++) {
        CP_WAIT2();                 // oldest group (stage it) complete
        __syncthreads();            // stage it-1 compute done by all warps
        if (it + 3 < NIT) {
            int nb = buf + 3; if (nb >= NSTAGE) nb -= NSTAGE;
            prefetch(it + 3, nb);
        } else {
            CP_COMMIT();            // keep wait_group arithmetic valid
        }

        uint32_t bufb = sb + buf * BUF_BYTES;
#pragma unroll
        for (int s = 0; s < 2; s++) {
            uint32_t ah[2][4], bh[4][4], bl[4][4];
            uint32_t aaddr = bufb + a_row * ROWB + s * 32 + a_colb;
            ldsm_x4(aaddr + AH_O, ah[0]);
            ldsm_x4(aaddr + AH_O + 16 * ROWB, ah[1]);
            uint32_t baddr = bufb + b_row * ROWB + s * 32 + b_colb;
#pragma unroll
            for (int j2 = 0; j2 < 4; j2++) {
                ldsm_x4(baddr + BH_O + j2 * 16 * ROWB, bh[j2]);
                ldsm_x4(baddr + BL_O + j2 * 16 * ROWB, bl[j2]);
            }
#pragma unroll
            for (int t = 0; t < 2; t++)
#pragma unroll
                for (int j = 0; j < 8; j++) {
                    const uint32_t* bhp = &bh[j >> 1][(j & 1) * 2];
                    const uint32_t* blp = &bl[j >> 1][(j & 1) * 2];
                    mma_fp16(acc[t][j], ah[t], bhp);
                    mma_fp16(acc[t][j], ah[t], blp);
                }
        }
        buf++; if (buf >= NSTAGE) buf = 0;
    }

    // ---- epilogue on register accumulators ----
#pragma unroll
    for (int t = 0; t < 2; t++) {
        int rbase = m0 + wm * 32 + t * 16 + (lane >> 2);
#pragma unroll
        for (int half = 0; half < 2; half++) {
            int row = rbase + half * 8;
            int s = row & (SEQ - 1);
#pragma unroll
            for (int j = 0; j < 8; j++) {
                int col = n0 + wn * 64 + j * 8 + (lane & 3) * 2;
                float x1 = acc[t][j][half * 2 + 0];
                float x2 = acc[t][j][half * 2 + 1];
                if (ep) {
                    int p = (col & 63) >> 1;
                    float cs = g_cos[s * 32 + p];
                    float sn = g_sin[s * 32 + p];
                    float r1 = x1 * cs - x2 * sn;
                    float r2 = fmaf(x1, sn, x2 * cs);
                    x1 = fmaxf(r1, 0.0f);
                    x2 = fmaxf(r2, 0.0f);
                }
                *(float2*)(C + (size_t)row * D_MODEL + col) = make_float2(x1, x2);
            }
        }
    }
}

// ---------------------------------------------------------------------------
// vk: zero + partial accumulation (512 CTAs) + atomicAdd
// ---------------------------------------------------------------------------
__global__ void zero_vk_kernel() {
    int i = blockIdx.x * 256 + threadIdx.x;
    if (i < BATCH * NHEADS * 65 * 64) g_VK[i] = 0.0f;
}

__global__ __launch_bounds__(256)
void vk_partial_kernel()
{
    __shared__ float ks[64][64];
    __shared__ float vs[64][64];

    const int bh = blockIdx.x;
    const int part = blockIdx.y;       // 0..7, 512 seq rows each
    const int b = bh >> 4;
    const int h = bh & 15;
    const int t = threadIdx.x;
    const int d  = t & 63;
    const int eg = t >> 6;

    const size_t base = (size_t)b * SEQ * D_MODEL + (size_t)h * 64;
    const int r0 = part * 512;

    float acc[16];
#pragma unroll
    for (int j = 0; j < 16; j++) acc[j] = 0.0f;
    float ksum = 0.0f;

    for (int c = 0; c < 8; c++) {
        for (int i = t; i < 64 * 64; i += 256) {
            int row = i >> 6, col = i & 63;
            size_t goff = base + (size_t)(r0 + c * 64 + row) * D_MODEL + col;
            ks[row][col] = g_K[goff];
            vs[row][col] = g_V[goff];
        }
        __syncthreads();
#pragma unroll 4
        for (int ss = 0; ss < 64; ss++) {
            float kv = ks[ss][d];
            if (eg == 0) ksum += kv;
#pragma unroll
            for (int j = 0; j < 16; j++)
                acc[j] = fmaf(vs[ss][eg * 16 + j], kv, acc[j]);
        }
        __syncthreads();
    }

    float* vkp = g_VK + (size_t)bh * 65 * 64;
#pragma unroll
    for (int j = 0; j < 16; j++)
        atomicAdd(&vkp[(eg * 16 + j) * 64 + d], acc[j]);
    if (eg == 0)
        atomicAdd(&vkp[64 * 64 + d], ksum);
}

// ---------------------------------------------------------------------------
// attn: writes fp16 directly (feeds final tensor-core GEMM)
// ---------------------------------------------------------------------------
__global__ __launch_bounds__(256)
void attn_kernel()
{
    __shared__ float vkS[65][64];
    const int bh = blockIdx.x;
    const int b = bh >> 4;
    const int h = bh & 15;
    const int t = threadIdx.x;

    const float* vkp = g_VK + (size_t)bh * 65 * 64;
    for (int i = t; i < 65 * 64; i += 256)
        vkS[i >> 6][i & 63] = vkp[i];
    __syncthreads();

    const int l = blockIdx.y * 256 + t;
    const size_t roff = ((size_t)(b * SEQ + l)) * D_MODEL + (size_t)h * 64;
    const float* qr = g_Q + roff;

    float q[64];
#pragma unroll
    for (int i = 0; i < 16; i++) {
        float4 v4 = ((const float4*)qr)[i];
        q[4 * i + 0] = v4.x; q[4 * i + 1] = v4.y;
        q[4 * i + 2] = v4.z; q[4 * i + 3] = v4.w;
    }

    float denom = 1e-6f;
#pragma unroll
    for (int d = 0; d < 64; d++) denom = fmaf(vkS[64][d], q[d], denom);
    float inv = 1.0f / denom;

    __half oh[64];
    for (int e = 0; e < 64; e++) {
        float num = 0.0f;
#pragma unroll
        for (int d = 0; d < 64; d++) num = fmaf(vkS[e][d], q[d], num);
        oh[e] = __float2half_rn(num * inv);
    }
#pragma unroll
    for (int i = 0; i < 8; i++)
        ((uint4*)(g_Ah + roff))[i] = ((uint4*)oh)[i];
}

// ---------------------------------------------------------------------------
// kernel_launch
// ---------------------------------------------------------------------------
extern "C" void kernel_launch(void* const* d_in, const int* in_sizes, int n_in,
                              void* d_out, int out_size)
{
    const float* x  = (const float*)d_in[0];
    const float* Wq = (const float*)d_in[1];
    const float* Wk = (const float*)d_in[2];
    const float* Wv = (const float*)d_in[3];
    const float* Wo = (const float*)d_in[4];
    float* out = (float*)d_out;

    float *qp, *kp, *vp;
    __half *xh, *ah, *wh, *wl;
    cudaGetSymbolAddress((void**)&qp, g_Q);
    cudaGetSymbolAddress((void**)&kp, g_K);
    cudaGetSymbolAddress((void**)&vp, g_V);
    cudaGetSymbolAddress((void**)&xh, g_Xh);
    cudaGetSymbolAddress((void**)&ah, g_Ah);
    cudaGetSymbolAddress((void**)&wh, g_Wh);
    cudaGetSymbolAddress((void**)&wl, g_Wl);
    const size_t WSZ = (size_t)D_MODEL * D_MODEL;

    cudaFuncSetAttribute(gemm_fp16x2, cudaFuncAttributeMaxDynamicSharedMemorySize, SMEM_GEMM);

    rope_table_kernel<<<(SEQ * 32 + 255) / 256, 256>>>();
    convx_kernel<<<(MROWS * D_MODEL / 4 + 255) / 256, 256>>>(x);

    dim3 tgrid(D_MODEL / 32, D_MODEL / 32);
    wtrans_kernel<<<tgrid, 256>>>(Wq, wh + 0 * WSZ, wl + 0 * WSZ);
    wtrans_kernel<<<tgrid, 256>>>(Wk, wh + 1 * WSZ, wl + 1 * WSZ);
    wtrans_kernel<<<tgrid, 256>>>(Wv, wh + 2 * WSZ, wl + 2 * WSZ);
    wtrans_kernel<<<tgrid, 256>>>(Wo, wh + 3 * WSZ, wl + 3 * WSZ);

    dim3 ggrid(D_MODEL / GB_BN, MROWS / GB_BM);   // (8, 128)
    gemm_fp16x2<<<ggrid, 256, SMEM_GEMM>>>(xh, wh + 0 * WSZ, wl + 0 * WSZ, qp, 1);
    gemm_fp16x2<<<ggrid, 256, SMEM_GEMM>>>(xh, wh + 1 * WSZ, wl + 1 * WSZ, kp, 1);
    gemm_fp16x2<<<ggrid, 256, SMEM_GEMM>>>(xh, wh + 2 * WSZ, wl + 2 * WSZ, vp, 0);

    zero_vk_kernel<<<(BATCH * NHEADS * 65 * 64 + 255) / 256, 256>>>();
    vk_partial_kernel<<<dim3(BATCH * NHEADS, 8), 256>>>();
    attn_kernel<<<dim3(BATCH * NHEADS, SEQ / 256), 256>>>();

    gemm_fp16x2<<<ggrid, 256, SMEM_GEMM>>>(ah, wh + 3 * WSZ, wl + 3 * WSZ, out, 0);
}